// round 5
// baseline (speedup 1.0000x reference)
#include <cuda_runtime.h>

// Problem constants (fixed by the reference)
#define BATCH    4
#define NPB      8192
#define KNBR     16
#define C        128
#define ROWS     (BATCH * NPB)   // 32768

// Tiling / pipeline
#define TM       32              // rows per tile
#define THREADS  256             // 4 producer warps + 4 consumer warps
#define HSTRIDE  132             // padded h row stride (floats), 16B aligned
#define NTILES   (ROWS / TM)     // 1024
#define GRID     456             // 3 blocks/SM on 152 SMs

// smem: just 2 h-buffers now (W^T lives in global, L1-cached)
#define SMEM_BYTES  (2 * TM * HSTRIDE * 4)

typedef unsigned long long u64;

__device__ float g_Wt[C * C];    // W transposed: [c][o]

__device__ __forceinline__ u64 fma2(u64 a, u64 b, u64 c) {
    u64 d;
    asm("fma.rn.f32x2 %0, %1, %2, %3;" : "=l"(d) : "l"(a), "l"(b), "l"(c));
    return d;
}
__device__ __forceinline__ u64 rep2(float v) {
    u64 d;
    asm("mov.b64 %0, {%1, %1};" : "=l"(d) : "f"(v));
    return d;
}
__device__ __forceinline__ float2 unpack2(u64 v) {
    float2 r;
    asm("mov.b64 {%0, %1}, %2;" : "=f"(r.x), "=f"(r.y) : "l"(v));
    return r;
}
__device__ __forceinline__ void bar_sync(int id) {
    asm volatile("bar.sync %0, 256;" :: "r"(id) : "memory");
}
__device__ __forceinline__ void bar_arrive(int id) {
    asm volatile("bar.arrive %0, 256;" :: "r"(id) : "memory");
}

// ---------------- prologue: W[o][c] -> g_Wt[c][o] ----------------
__global__ void transpose_W_kernel(const float* __restrict__ W)
{
    __shared__ float s[32][33];
    const int bi = blockIdx.x >> 2;      // row tile of W
    const int bj = blockIdx.x & 3;       // col tile of W
    const int tx = threadIdx.x & 31;
    const int ty = threadIdx.x >> 5;     // 0..31 (1024 threads)

    s[ty][tx] = W[(bi * 32 + ty) * C + bj * 32 + tx];
    __syncthreads();
    g_Wt[(bj * 32 + ty) * C + bi * 32 + tx] = s[tx][ty];
}

__global__ __launch_bounds__(THREADS, 3)
void gin_fused_kernel(const float* __restrict__ x,
                      const void* __restrict__ ei_raw,
                      const float* __restrict__ bias,
                      const float* __restrict__ epsp,
                      float* __restrict__ out)
{
    extern __shared__ float hbuf[];      // 2 x (TM x HSTRIDE)

    const int tid = threadIdx.x;

    // ---------- dtype sniff: int64 (odd words all 0) vs int32 ----------
    const int* w32 = (const int*)ei_raw;
    int orv = 0;
    #pragma unroll
    for (int t = 0; t < 64; t++) orv |= w32[t * 8192 + 1];
    const bool is64 = (orv == 0);
    const long long* w64 = (const long long*)ei_raw;

    const float oe = 1.0f + epsp[0];
    const bool producer = (tid < 128);

    int iter = 0;
    for (int tile = blockIdx.x; tile < NTILES; tile += GRID, iter++) {
        const int s = iter & 1;
        const int row0 = tile * TM;
        float* sh = hbuf + s * TM * HSTRIDE;

        if (producer) {
            // 8 threads per row; each owns one 16B slice of every 128B line.
            const int rl = tid >> 3;        // 0..15 : rows rl and rl+16
            const int p  = tid & 7;

            if (iter >= 2) bar_sync(3 + s);     // buffer s consumed?

            #pragma unroll
            for (int hh = 0; hh < 2; hh++) {
                const int row = row0 + rl + 16 * hh;
                const int bbase = (row >> 13) << 13;     // b * 8192

                int idxs[KNBR];
                if (!is64) {
                    const int4* ip = (const int4*)(w32 + (size_t)row * KNBR);
                    #pragma unroll
                    for (int q = 0; q < 4; q++) {
                        int4 v = ip[q];
                        idxs[4*q+0] = v.x; idxs[4*q+1] = v.y;
                        idxs[4*q+2] = v.z; idxs[4*q+3] = v.w;
                    }
                } else {
                    #pragma unroll
                    for (int k = 0; k < KNBR; k++)
                        idxs[k] = (int)w64[(size_t)row * KNBR + k];
                }
                #pragma unroll
                for (int k = 0; k < KNBR; k++)
                    idxs[k] = (bbase + idxs[k]) << 7;

                const float* xs = x + ((size_t)row << 7) + 4 * p;
                float4 acc[4];
                #pragma unroll
                for (int j = 0; j < 4; j++) {
                    float4 v = *(const float4*)(xs + 32 * j);
                    acc[j].x = v.x * oe; acc[j].y = v.y * oe;
                    acc[j].z = v.z * oe; acc[j].w = v.w * oe;
                }
                #pragma unroll 4
                for (int k = 0; k < KNBR; k++) {
                    const float* xn = x + idxs[k] + 4 * p;
                    #pragma unroll
                    for (int j = 0; j < 4; j++) {
                        float4 v = *(const float4*)(xn + 32 * j);
                        acc[j].x += v.x; acc[j].y += v.y;
                        acc[j].z += v.z; acc[j].w += v.w;
                    }
                }
                #pragma unroll
                for (int j = 0; j < 4; j++)
                    *(float4*)(sh + (rl + 16 * hh) * HSTRIDE + 32 * j + 4 * p) = acc[j];
            }
            bar_arrive(1 + s);   // buffer s full
        } else {
            // consumer: 8 rows x 4 cols per thread; W^T from global (L1-hit)
            const int ct = tid - 128;
            const int ty = ct >> 5;          // 0..3 : rows ty*8 .. ty*8+7
            const int tx = ct & 31;          // cols 4*tx .. 4*tx+3

            bar_sync(1 + s);                 // wait buffer s full

            u64 acc[8][2];
            #pragma unroll
            for (int i = 0; i < 8; i++) { acc[i][0] = 0ull; acc[i][1] = 0ull; }

            const float* hp = sh + ty * 8 * HSTRIDE;
            const float* wp = g_Wt + 4 * tx;

            #pragma unroll 2
            for (int c = 0; c < C; c += 4) {
                ulonglong2 w0 = *(const ulonglong2*)(wp + (c + 0) * C);
                ulonglong2 w1 = *(const ulonglong2*)(wp + (c + 1) * C);
                ulonglong2 w2 = *(const ulonglong2*)(wp + (c + 2) * C);
                ulonglong2 w3 = *(const ulonglong2*)(wp + (c + 3) * C);
                #pragma unroll
                for (int i = 0; i < 8; i++) {
                    float4 h = *(const float4*)(hp + i * HSTRIDE + c);
                    u64 hx = rep2(h.x), hy = rep2(h.y), hz = rep2(h.z), hw = rep2(h.w);
                    acc[i][0] = fma2(hx, w0.x, acc[i][0]);
                    acc[i][1] = fma2(hx, w0.y, acc[i][1]);
                    acc[i][0] = fma2(hy, w1.x, acc[i][0]);
                    acc[i][1] = fma2(hy, w1.y, acc[i][1]);
                    acc[i][0] = fma2(hz, w2.x, acc[i][0]);
                    acc[i][1] = fma2(hz, w2.y, acc[i][1]);
                    acc[i][0] = fma2(hw, w3.x, acc[i][0]);
                    acc[i][1] = fma2(hw, w3.y, acc[i][1]);
                }
            }
            bar_arrive(3 + s);               // buffer s consumed

            float4 b4 = *(const float4*)(bias + 4 * tx);
            #pragma unroll
            for (int i = 0; i < 8; i++) {
                float2 a0 = unpack2(acc[i][0]);
                float2 a1 = unpack2(acc[i][1]);
                float4 o;
                o.x = fmaxf(a0.x + b4.x, 0.f);
                o.y = fmaxf(a0.y + b4.y, 0.f);
                o.z = fmaxf(a1.x + b4.z, 0.f);
                o.w = fmaxf(a1.y + b4.w, 0.f);
                *(float4*)(out + (size_t)(row0 + ty * 8 + i) * C + 4 * tx) = o;
            }
        }
    }
}

extern "C" void kernel_launch(void* const* d_in, const int* in_sizes, int n_in,
                              void* d_out, int out_size)
{
    const float* x    = (const float*)d_in[0];
    const void*  ei   = d_in[1];
    const float* W    = (const float*)d_in[2];
    const float* bias = (const float*)d_in[3];
    const float* eps  = (const float*)d_in[4];
    float*       out  = (float*)d_out;

    transpose_W_kernel<<<16, 1024>>>(W);
    gin_fused_kernel<<<GRID, THREADS, SMEM_BYTES>>>(x, ei, bias, eps, out);
}

// round 6
// speedup vs baseline: 1.2369x; 1.2369x over previous
#include <cuda_runtime.h>

#define KNBR     16
#define C        128
#define ROWS     32768
#define TM       32
#define THREADS  256            // 4 producer warps + 4 consumer warps
#define NTILES   (ROWS / TM)    // 1024
#define GRID     304            // 2 blocks/SM

#define HT_FLOATS (C * TM)      // transposed h buffer: 128 c x 32 m = 4096 floats
#define SMEM_FLOATS (C * C + 2 * HT_FLOATS)
#define SMEM_BYTES  (SMEM_FLOATS * 4)   // 96 KB

typedef unsigned long long u64;

__device__ __forceinline__ u64 fma2(u64 a, u64 b, u64 c) {
    u64 d; asm("fma.rn.f32x2 %0, %1, %2, %3;" : "=l"(d) : "l"(a), "l"(b), "l"(c)); return d;
}
__device__ __forceinline__ u64 add2(u64 a, u64 b) {
    u64 d; asm("add.rn.f32x2 %0, %1, %2;" : "=l"(d) : "l"(a), "l"(b)); return d;
}
__device__ __forceinline__ u64 mul2(u64 a, u64 b) {
    u64 d; asm("mul.rn.f32x2 %0, %1, %2;" : "=l"(d) : "l"(a), "l"(b)); return d;
}
__device__ __forceinline__ u64 rep2(float v) {
    u64 d; asm("mov.b64 %0, {%1, %1};" : "=l"(d) : "f"(v)); return d;
}
__device__ __forceinline__ float2 unpack2(u64 v) {
    float2 r; asm("mov.b64 {%0, %1}, %2;" : "=f"(r.x), "=f"(r.y) : "l"(v)); return r;
}
__device__ __forceinline__ void bar_sync(int id) {
    asm volatile("bar.sync %0, 256;" :: "r"(id) : "memory");
}
__device__ __forceinline__ void bar_arrive(int id) {
    asm volatile("bar.arrive %0, 256;" :: "r"(id) : "memory");
}

__global__ __launch_bounds__(THREADS, 2)
void gin_fused_kernel(const float* __restrict__ x,
                      const void* __restrict__ ei_raw,
                      const float* __restrict__ W,
                      const float* __restrict__ bias,
                      const float* __restrict__ epsp,
                      float* __restrict__ out)
{
    extern __shared__ float smem[];
    float* sWt  = smem;                 // 128x128 : W^T [c][o]
    float* hbuf = smem + C * C;         // 2 x HT_FLOATS (transposed+swizzled h)
    float* stg  = hbuf;                 // alias: 32x33 transpose staging (1056 floats)

    const int tid = threadIdx.x;

    // ---------- dtype sniff: int64 (odd words all 0) vs int32 ----------
    const int* w32 = (const int*)ei_raw;
    int orv = 0;
    #pragma unroll
    for (int t = 0; t < 64; t++) orv |= w32[t * 8192 + 1];
    const bool is64 = (orv == 0);
    const long long* w64 = (const long long*)ei_raw;

    // ---------- one-time: transpose W into sWt[c][o], 16 tiles of 32x32 ----------
    {
        const int trow = tid >> 5;      // 0..7
        const int tcol = tid & 31;
        for (int t = 0; t < 16; t++) {
            const int bi = t >> 2, bj = t & 3;
            #pragma unroll
            for (int rr = 0; rr < 4; rr++)
                stg[(trow + 8 * rr) * 33 + tcol] =
                    W[(size_t)(bi * 32 + trow + 8 * rr) * C + bj * 32 + tcol];
            __syncthreads();
            #pragma unroll
            for (int rr = 0; rr < 4; rr++)
                sWt[(size_t)(bj * 32 + trow + 8 * rr) * C + bi * 32 + tcol] =
                    stg[tcol * 33 + trow + 8 * rr];
            __syncthreads();
        }
    }

    const float oe  = 1.0f + epsp[0];
    const u64   oe2 = rep2(oe);
    const bool producer = (tid < 128);

    int iter = 0;
    for (int tile = blockIdx.x; tile < NTILES; tile += GRID, iter++) {
        const int s = iter & 1;
        const int row0 = tile * TM;
        float* sh = hbuf + s * HT_FLOATS;

        if (producer) {
            // 8 threads/row, each owns a 16B slice of every 128B line.
            const int rl = tid >> 3;        // 0..15 : rows rl and rl+16
            const int p  = tid & 7;
            const int X4 = 4 * p;           // swizzle term (== c & 0x1C for this thread)

            if (iter >= 2) bar_sync(3 + s);     // buffer s consumed?

            #pragma unroll
            for (int hh = 0; hh < 2; hh++) {
                const int lrow = rl + 16 * hh;
                const int row  = row0 + lrow;
                const int bbase = (row >> 13) << 13;        // b * 8192
                const int msw = lrow ^ X4;                   // swizzled m (conflict-free)

                int idxs[KNBR];
                if (!is64) {
                    const int4* ip = (const int4*)(w32 + (size_t)row * KNBR);
                    #pragma unroll
                    for (int q = 0; q < 4; q++) {
                        int4 v = ip[q];
                        idxs[4*q+0] = v.x; idxs[4*q+1] = v.y;
                        idxs[4*q+2] = v.z; idxs[4*q+3] = v.w;
                    }
                } else {
                    #pragma unroll
                    for (int k = 0; k < KNBR; k++)
                        idxs[k] = (int)w64[(size_t)row * KNBR + k];
                }
                #pragma unroll
                for (int k = 0; k < KNBR; k++)
                    idxs[k] = (bbase + idxs[k]) << 7;

                // accumulate 16 floats (channels 32j+4p..+3) as 8 f32x2 pairs
                const float* xs = x + ((size_t)row << 7) + 4 * p;
                u64 a[8];
                #pragma unroll
                for (int j = 0; j < 4; j++) {
                    ulonglong2 v = *(const ulonglong2*)(xs + 32 * j);
                    a[2*j]   = mul2(v.x, oe2);
                    a[2*j+1] = mul2(v.y, oe2);
                }
                #pragma unroll 4
                for (int k = 0; k < KNBR; k++) {
                    const float* xn = x + idxs[k] + 4 * p;
                    #pragma unroll
                    for (int j = 0; j < 4; j++) {
                        ulonglong2 v = *(const ulonglong2*)(xn + 32 * j);
                        a[2*j]   = add2(a[2*j],   v.x);
                        a[2*j+1] = add2(a[2*j+1], v.y);
                    }
                }

                // transposed+swizzled store: sh[32*c + (lrow ^ (c&0x1C))], c = 32j+4p+q
                #pragma unroll
                for (int j = 0; j < 4; j++) {
                    const int cb = 32 * j + 4 * p;
                    float2 f0 = unpack2(a[2*j]);
                    float2 f1 = unpack2(a[2*j+1]);
                    sh[((cb + 0) << 5) + msw] = f0.x;
                    sh[((cb + 1) << 5) + msw] = f0.y;
                    sh[((cb + 2) << 5) + msw] = f1.x;
                    sh[((cb + 3) << 5) + msw] = f1.y;
                }
            }
            bar_arrive(1 + s);   // buffer s full
        } else {
            // consumer: 8 rows (4 native f32x2 pairs) x 4 cols per thread
            const int ct  = tid - 128;
            const int ty8 = (ct >> 5) << 3;     // row base 0/8/16/24
            const int tx  = ct & 31;            // cols 4tx..4tx+3

            bar_sync(1 + s);                    // wait buffer s full

            u64 acc[4][4];                      // [col][row-pair]
            #pragma unroll
            for (int i = 0; i < 4; i++)
                #pragma unroll
                for (int j = 0; j < 4; j++) acc[i][j] = 0ull;

            #pragma unroll 4
            for (int c = 0; c < C; c++) {
                float4 w4 = *(const float4*)(sWt + (c << 7) + 4 * tx);  // spread
                const int X = c & 0x1C;
                const float* hc = sh + (c << 5);
                ulonglong2 hA = *(const ulonglong2*)(hc + ((ty8 + 0) ^ X)); // rows +0..3 (bcast)
                ulonglong2 hB = *(const ulonglong2*)(hc + ((ty8 + 4) ^ X)); // rows +4..7
                u64 q0 = rep2(w4.x), q1 = rep2(w4.y), q2 = rep2(w4.z), q3 = rep2(w4.w);
                acc[0][0] = fma2(q0, hA.x, acc[0][0]);
                acc[0][1] = fma2(q0, hA.y, acc[0][1]);
                acc[0][2] = fma2(q0, hB.x, acc[0][2]);
                acc[0][3] = fma2(q0, hB.y, acc[0][3]);
                acc[1][0] = fma2(q1, hA.x, acc[1][0]);
                acc[1][1] = fma2(q1, hA.y, acc[1][1]);
                acc[1][2] = fma2(q1, hB.x, acc[1][2]);
                acc[1][3] = fma2(q1, hB.y, acc[1][3]);
                acc[2][0] = fma2(q2, hA.x, acc[2][0]);
                acc[2][1] = fma2(q2, hA.y, acc[2][1]);
                acc[2][2] = fma2(q2, hB.x, acc[2][2]);
                acc[2][3] = fma2(q2, hB.y, acc[2][3]);
                acc[3][0] = fma2(q3, hA.x, acc[3][0]);
                acc[3][1] = fma2(q3, hA.y, acc[3][1]);
                acc[3][2] = fma2(q3, hB.x, acc[3][2]);
                acc[3][3] = fma2(q3, hB.y, acc[3][3]);
            }
            bar_arrive(3 + s);                  // buffer s consumed

            const float4 b4 = *(const float4*)(bias + 4 * tx);
            #pragma unroll
            for (int pp = 0; pp < 4; pp++) {
                float2 a0 = unpack2(acc[0][pp]);
                float2 a1 = unpack2(acc[1][pp]);
                float2 a2 = unpack2(acc[2][pp]);
                float2 a3 = unpack2(acc[3][pp]);
                float4 o0, o1;
                o0.x = fmaxf(a0.x + b4.x, 0.f);
                o0.y = fmaxf(a1.x + b4.y, 0.f);
                o0.z = fmaxf(a2.x + b4.z, 0.f);
                o0.w = fmaxf(a3.x + b4.w, 0.f);
                o1.x = fmaxf(a0.y + b4.x, 0.f);
                o1.y = fmaxf(a1.y + b4.y, 0.f);
                o1.z = fmaxf(a2.y + b4.z, 0.f);
                o1.w = fmaxf(a3.y + b4.w, 0.f);
                const size_t rbase = (size_t)(row0 + ty8 + 2 * pp) * C + 4 * tx;
                *(float4*)(out + rbase)     = o0;
                *(float4*)(out + rbase + C) = o1;
            }
        }
    }
}

extern "C" void kernel_launch(void* const* d_in, const int* in_sizes, int n_in,
                              void* d_out, int out_size)
{
    const float* x    = (const float*)d_in[0];
    const void*  ei   = d_in[1];
    const float* W    = (const float*)d_in[2];
    const float* bias = (const float*)d_in[3];
    const float* eps  = (const float*)d_in[4];
    float*       out  = (float*)d_out;

    cudaFuncSetAttribute(gin_fused_kernel,
                         cudaFuncAttributeMaxDynamicSharedMemorySize, SMEM_BYTES);

    gin_fused_kernel<<<GRID, THREADS, SMEM_BYTES>>>(x, ei, W, bias, eps, out);
}